// round 14
// baseline (speedup 1.0000x reference)
#include <cuda_runtime.h>
#include <cuda_fp16.h>
#include <math.h>
#include <stdint.h>

// Problem constants
#define Nn   2048
#define CIN  2
#define Hh   32
#define EMB  16
#define HOR  12
#define Bb   32
#define Tt   16
#define KD   2048
#define GSTRIDE (Nn * 1024)
#define KSPLIT 1024

// Device scratch
__device__ __half g_Ah [Nn * Nn];       // adjacency fp16, [m][k] row-major
__device__ __half g_Rh [Nn * 1024];     // H fp16, [node(k)][b*32+h(n)]
__device__ __half g_Bxh[Nn * 1024];     // X all timesteps fp16
__device__ __half g_Gh [2 * GSTRIDE];   // split-K halves (Gx prologue only)
__device__ float  g_Gx [Nn * 1024];     // A @ X_all (summed, fp32)
__device__ float  g_C  [Nn * Bb * Hh];  // cell state, fragment-linear (fused-private)
__device__ float  g_Hf [Nn * Bb * Hh];  // fp32 h [(n*32+b)*32+h], written at t=15
__device__ __half g_Whsp[48 * 128];     // folded gate weights, packed fp16

// ---------------------------------------------------------------------------
__device__ __forceinline__ float fsig(float x) { return 1.0f / (1.0f + __expf(-x)); }
__device__ __forceinline__ float ftanh(float x) { return 2.0f / (1.0f + __expf(-2.0f * x)) - 1.0f; }

__device__ __forceinline__ void cp16(void* dst, const void* src) {
    uint32_t s = (uint32_t)__cvta_generic_to_shared(dst);
    asm volatile("cp.async.cg.shared.global [%0], [%1], 16;" :: "r"(s), "l"(src));
}
#define CP_COMMIT() asm volatile("cp.async.commit_group;" ::: "memory")
template <int N> __device__ __forceinline__ void cp_wait() {
    asm volatile("cp.async.wait_group %0;" :: "n"(N) : "memory");
}

__device__ __forceinline__ void ldsm_x4(uint32_t (&r)[4], const void* p) {
    uint32_t a = (uint32_t)__cvta_generic_to_shared(p);
    asm volatile("ldmatrix.sync.aligned.m8n8.x4.shared.b16 {%0,%1,%2,%3}, [%4];"
                 : "=r"(r[0]), "=r"(r[1]), "=r"(r[2]), "=r"(r[3]) : "r"(a));
}
__device__ __forceinline__ void ldsm_x4_t(uint32_t (&r)[4], const void* p) {
    uint32_t a = (uint32_t)__cvta_generic_to_shared(p);
    asm volatile("ldmatrix.sync.aligned.m8n8.x4.trans.shared.b16 {%0,%1,%2,%3}, [%4];"
                 : "=r"(r[0]), "=r"(r[1]), "=r"(r[2]), "=r"(r[3]) : "r"(a));
}
__device__ __forceinline__ void mma_fp16(float (&d)[4], const uint32_t (&a)[4], const uint32_t* b) {
    asm volatile(
        "mma.sync.aligned.m16n8k16.row.col.f32.f16.f16.f32 "
        "{%0,%1,%2,%3}, {%4,%5,%6,%7}, {%8,%9}, {%0,%1,%2,%3};"
        : "+f"(d[0]), "+f"(d[1]), "+f"(d[2]), "+f"(d[3])
        : "r"(a[0]), "r"(a[1]), "r"(a[2]), "r"(a[3]), "r"(b[0]), "r"(b[1]));
}

// ---------------------------------------------------------------------------
// A = softmax(relu(E1 @ E2^T)) row-major [m][k], fp16
// ---------------------------------------------------------------------------
__global__ __launch_bounds__(256) void adj_kernel(const float* __restrict__ E1,
                                                  const float* __restrict__ E2) {
    int r = blockIdx.x;
    int tid = threadIdx.x;
    __shared__ float e1[EMB];
    __shared__ float red[256];
    if (tid < EMB) e1[tid] = E1[r * EMB + tid];
    __syncthreads();

    float v[8];
    float mx = -1e30f;
#pragma unroll
    for (int i = 0; i < 8; i++) {
        int c = tid + i * 256;
        float d = 0.f;
#pragma unroll
        for (int e = 0; e < EMB; e++) d += e1[e] * E2[c * EMB + e];
        d = fmaxf(d, 0.f);
        v[i] = d;
        mx = fmaxf(mx, d);
    }
    red[tid] = mx; __syncthreads();
    for (int s = 128; s > 0; s >>= 1) {
        if (tid < s) red[tid] = fmaxf(red[tid], red[tid + s]);
        __syncthreads();
    }
    mx = red[0]; __syncthreads();

    float sum = 0.f;
#pragma unroll
    for (int i = 0; i < 8; i++) { v[i] = expf(v[i] - mx); sum += v[i]; }
    red[tid] = sum; __syncthreads();
    for (int s = 128; s > 0; s >>= 1) {
        if (tid < s) red[tid] += red[tid + s];
        __syncthreads();
    }
    float inv = 1.0f / red[0];
#pragma unroll
    for (int i = 0; i < 8; i++)
        g_Ah[(size_t)r * Nn + tid + i * 256] = __float2half_rn(v[i] * inv);
}

// ---------------------------------------------------------------------------
__global__ __launch_bounds__(256) void buildx_kernel(const float* __restrict__ x) {
    int idx = blockIdx.x * 256 + threadIdx.x;
    int n = idx >> 10;
    int q = idx & 1023;
    int t = q >> 6;
    int r6 = q & 63;
    int b = r6 >> 1;
    int c = r6 & 1;
    g_Bxh[idx] = __float2half_rn(x[(((size_t)b * Tt + t) * Nn + n) * CIN + c]);
}

// folded gate weights -> packed fp16 global (once)
__global__ __launch_bounds__(256) void whs_prep(const float* __restrict__ Wx,
                                                const float* __restrict__ bx,
                                                const float* __restrict__ Wh,
                                                const float* __restrict__ bh) {
    int i = blockIdx.x * 256 + threadIdx.x;
    int k = i >> 7, g = i & 127;
    float v;
    if (k < 32)       v = Wh[k * 128 + g];
    else if (k == 32) v = Wx[g];
    else if (k == 33) v = Wx[128 + g];
    else if (k == 34) v = bx[g] + bh[g];
    else              v = 0.f;
    g_Whsp[i] = __float2half_rn(v);
}

// g_Gx = (fp32) g_Gh[0..] + g_Gh[GSTRIDE..]
__global__ __launch_bounds__(256) void addx_kernel() {
    int i = blockIdx.x * 256 + threadIdx.x;
    __half2 a = ((const __half2*)g_Gh)[i];
    __half2 b = ((const __half2*)(g_Gh + GSTRIDE))[i];
    ((float2*)g_Gx)[i] = make_float2(__low2float(a) + __low2float(b),
                                     __high2float(a) + __high2float(b));
}

// ---------------------------------------------------------------------------
// Split-K GEMM (R12 config, known-good) — used ONCE for Gx = A @ X_all
// ---------------------------------------------------------------------------
#define APITCH 40
#define BPITCH 136
#define ASZH (128 * APITCH)
#define BSZH (32 * BPITCH)
#define SSTAGEH (ASZH + BSZH)
#define KSP_SMEM (4 * SSTAGEH * (int)sizeof(__half))   // 75776 B

__global__ void __launch_bounds__(128, 2)
sgemm_ksp(const __half* __restrict__ Ah, const __half* __restrict__ Bh,
          __half* __restrict__ C) {
    extern __shared__ __half smem[];
    int tid = threadIdx.x;
    int lane = tid & 31;
    int w = tid >> 5;
    int bm0 = blockIdx.y * 128;
    int bn0 = blockIdx.x * 128;
    int kBase = blockIdx.z * KSPLIT;
    C += (size_t)blockIdx.z * GSTRIDE;
    int wm0 = (w & 1) * 64;
    int wn0 = (w >> 1) * 64;

    float acc[4][8][4];
#pragma unroll
    for (int mt = 0; mt < 4; mt++)
#pragma unroll
        for (int nt = 0; nt < 8; nt++)
#pragma unroll
            for (int i = 0; i < 4; i++) acc[mt][nt][i] = 0.f;

    auto load_stage = [&](int s, int k0) {
        __half* sA = smem + (s & 3) * SSTAGEH;
        __half* sB = sA + ASZH;
#pragma unroll
        for (int i = 0; i < 4; i++) {
            int ch = tid + i * 128;
            int r = ch >> 2;
            int c = ch & 3;
            cp16(sA + r * APITCH + c * 8,
                 Ah + (size_t)(bm0 + r) * KD + kBase + k0 + c * 8);
        }
#pragma unroll
        for (int i = 0; i < 4; i++) {
            int ch = tid + i * 128;
            int r = ch >> 4;
            int c = ch & 15;
            cp16(sB + r * BPITCH + c * 8,
                 Bh + (size_t)(kBase + k0 + r) * 1024 + bn0 + c * 8);
        }
    };

    load_stage(0, 0);  CP_COMMIT();
    load_stage(1, 32); CP_COMMIT();
    load_stage(2, 64); CP_COMMIT();

    const int NIT = KSPLIT / 32;
    for (int it = 0; it < NIT; ++it) {
        if (it + 2 < NIT)      cp_wait<2>();
        else if (it + 1 < NIT) cp_wait<1>();
        else                   cp_wait<0>();
        __syncthreads();
        if (it + 3 < NIT) {
            load_stage(it + 3, (it + 3) * 32);
            CP_COMMIT();
        }

        const __half* sA = smem + (it & 3) * SSTAGEH;
        const __half* sB = sA + ASZH;
#pragma unroll
        for (int kk = 0; kk < 2; kk++) {
            uint32_t a[4][4];
#pragma unroll
            for (int mt = 0; mt < 4; mt++) {
                ldsm_x4(a[mt], sA + (wm0 + mt * 16 + (lane & 15)) * APITCH
                               + kk * 16 + ((lane >> 4) << 3));
            }
            uint32_t b[8][2];
#pragma unroll
            for (int np = 0; np < 4; np++) {
                uint32_t t4[4];
                ldsm_x4_t(t4, sB + (kk * 16 + (lane & 15)) * BPITCH
                              + wn0 + np * 16 + ((lane >> 4) << 3));
                b[np * 2][0] = t4[0]; b[np * 2][1] = t4[1];
                b[np * 2 + 1][0] = t4[2]; b[np * 2 + 1][1] = t4[3];
            }
#pragma unroll
            for (int mt = 0; mt < 4; mt++)
#pragma unroll
                for (int nt = 0; nt < 8; nt++) mma_fp16(acc[mt][nt], a[mt], b[nt]);
        }
        __syncthreads();
    }

#pragma unroll
    for (int mt = 0; mt < 4; mt++) {
        int r0 = bm0 + wm0 + mt * 16 + (lane >> 2);
#pragma unroll
        for (int nt = 0; nt < 8; nt++) {
            int c0 = bn0 + wn0 + nt * 8 + 2 * (lane & 3);
            *(__half2*)&C[(size_t)r0 * 1024 + c0] = __floats2half2_rn(acc[mt][nt][0], acc[mt][nt][1]);
            *(__half2*)&C[(size_t)(r0 + 8) * 1024 + c0] = __floats2half2_rn(acc[mt][nt][2], acc[mt][nt][3]);
        }
    }
}

// ---------------------------------------------------------------------------
// FUSED step kernel: G-tile (full K) + LSTM epilogue. No G global round-trip.
// Grid (16 n-tiles, 16 m-tiles) = 256 CTAs x 128 threads, CTA tile 128m x 64n.
// ---------------------------------------------------------------------------
#define FBPITCH 72
#define FASZ (128 * APITCH)            // 5120 halves
#define FBSZ (32 * FBPITCH)            // 2304 halves
#define FSTG (FASZ + FBSZ)             // 7424 halves
#define FSMEM (4 * FSTG * (int)sizeof(__half))   // 59392 B
#define GS_P 40
#define WHS_OFF (256 * GS_P)           // Gs: 256 rows x 40 = 10240 halves

__global__ void __launch_bounds__(128, 2)
fused_step(const __half* __restrict__ Ah, int t) {
    extern __shared__ __half smem[];
    int tid = threadIdx.x;
    int lane = tid & 31;
    int w = tid >> 5;
    int m0 = blockIdx.y * 128;           // node base
    int bn0 = blockIdx.x * 64;           // B col base
    int b0g = blockIdx.x * 2;            // batch base (2 batches per tile)
    int wm0 = (w & 1) * 64;
    int wn0 = (w >> 1) * 32;

    float acc[4][4][4];
#pragma unroll
    for (int mt = 0; mt < 4; mt++)
#pragma unroll
        for (int nt = 0; nt < 4; nt++)
#pragma unroll
            for (int i = 0; i < 4; i++) acc[mt][nt][i] = 0.f;

    auto load_stage = [&](int s, int k0) {
        __half* sA = smem + (s & 3) * FSTG;
        __half* sB = sA + FASZ;
#pragma unroll
        for (int i = 0; i < 4; i++) {
            int ch = tid + i * 128;
            int r = ch >> 2;
            int c = ch & 3;
            cp16(sA + r * APITCH + c * 8,
                 Ah + (size_t)(m0 + r) * KD + k0 + c * 8);
        }
#pragma unroll
        for (int i = 0; i < 2; i++) {
            int ch = tid + i * 128;
            int r = ch >> 3;
            int c = ch & 7;
            cp16(sB + r * FBPITCH + c * 8,
                 g_Rh + (size_t)(k0 + r) * 1024 + bn0 + c * 8);
        }
    };

    load_stage(0, 0);  CP_COMMIT();
    load_stage(1, 32); CP_COMMIT();
    load_stage(2, 64); CP_COMMIT();

    const int NIT = KD / 32;   // 64
    for (int it = 0; it < NIT; ++it) {
        if (it + 2 < NIT)      cp_wait<2>();
        else if (it + 1 < NIT) cp_wait<1>();
        else                   cp_wait<0>();
        __syncthreads();
        if (it + 3 < NIT) {
            load_stage(it + 3, (it + 3) * 32);
            CP_COMMIT();
        }

        const __half* sA = smem + (it & 3) * FSTG;
        const __half* sB = sA + FASZ;
#pragma unroll
        for (int kk = 0; kk < 2; kk++) {
            uint32_t a[4][4];
#pragma unroll
            for (int mt = 0; mt < 4; mt++) {
                ldsm_x4(a[mt], sA + (wm0 + mt * 16 + (lane & 15)) * APITCH
                               + kk * 16 + ((lane >> 4) << 3));
            }
            uint32_t b[4][2];
#pragma unroll
            for (int np = 0; np < 2; np++) {
                uint32_t t4[4];
                ldsm_x4_t(t4, sB + (kk * 16 + (lane & 15)) * FBPITCH
                              + wn0 + np * 16 + ((lane >> 4) << 3));
                b[np * 2][0] = t4[0]; b[np * 2][1] = t4[1];
                b[np * 2 + 1][0] = t4[2]; b[np * 2 + 1][1] = t4[3];
            }
#pragma unroll
            for (int mt = 0; mt < 4; mt++)
#pragma unroll
                for (int nt = 0; nt < 4; nt++) mma_fp16(acc[mt][nt], a[mt], b[nt]);
        }
        __syncthreads();
    }

    // ---------------- LSTM epilogue (in-CTA, full-K gates) ----------------
    __half* Gs  = smem;                // [256 lstm rows][GS_P]
    __half* Whs = smem + WHS_OFF;      // [48][BPITCH]

    __syncthreads();   // all reads of stage buffers done

    // async-load folded gate weights while staging acc
#pragma unroll
    for (int i = 0; i < 6; i++) {
        int ch = tid + i * 128;
        int r = ch >> 4, c = ch & 15;
        cp16(Whs + r * BPITCH + c * 8, g_Whsp + r * 128 + c * 8);
    }
    CP_COMMIT();

    // stage acc -> Gs, lstm-row-major: row = node_local*2 + b_local, col = h
#pragma unroll
    for (int mt = 0; mt < 4; mt++) {
#pragma unroll
        for (int nt = 0; nt < 4; nt++) {
#pragma unroll
            for (int rs = 0; rs < 2; rs++) {
                int mrow = wm0 + mt * 16 + (lane >> 2) + rs * 8;
                int col = wn0 + nt * 8 + 2 * (lane & 3);
                int rloc = mrow * 2 + (col >> 5);
                int h = col & 31;
                *(__half2*)&Gs[rloc * GS_P + h] =
                    __floats2half2_rn(acc[mt][nt][rs * 2], acc[mt][nt][rs * 2 + 1]);
            }
        }
    }
    cp_wait<0>();
    __syncthreads();

    int cta = blockIdx.y * 16 + blockIdx.x;
    int cole = 2 * (lane & 3);
    float2* Cp = (float2*)g_C;

#pragma unroll 1
    for (int mtile = 0; mtile < 4; mtile++) {
        int wrow = w * 64 + mtile * 16;
        int rl = wrow + (lane >> 2);
        int node_lo = m0 + (rl >> 1), b_lo = b0g + (rl & 1);
        int rh = rl + 8;
        int node_hi = m0 + (rh >> 1), b_hi = b0g + (rh & 1);
        float2 axlo = *(const float2*)&g_Gx[(size_t)node_lo * 1024 + t * 64 + b_lo * 2];
        float2 axhi = *(const float2*)&g_Gx[(size_t)node_hi * 1024 + t * 64 + b_hi * 2];

        float acc2[16][4];
#pragma unroll
        for (int nt = 0; nt < 16; nt++)
#pragma unroll
            for (int i = 0; i < 4; i++) acc2[nt][i] = 0.f;

#pragma unroll
        for (int kk = 0; kk < 3; kk++) {
            uint32_t a[4];
            if (kk < 2) {
                ldsm_x4(a, Gs + (wrow + (lane & 15)) * GS_P + kk * 16 + ((lane >> 4) << 3));
            } else {
                int sel = lane & 3;
                __half2 hlo = __floats2half2_rn(axlo.x, axlo.y);
                __half2 hhi = __floats2half2_rn(axhi.x, axhi.y);
                __half2 one = __floats2half2_rn(1.0f, 0.0f);
                uint32_t ulo = *reinterpret_cast<uint32_t*>(&hlo);
                uint32_t uhi = *reinterpret_cast<uint32_t*>(&hhi);
                uint32_t uon = *reinterpret_cast<uint32_t*>(&one);
                a[0] = (sel == 0) ? ulo : ((sel == 1) ? uon : 0u);
                a[1] = (sel == 0) ? uhi : ((sel == 1) ? uon : 0u);
                a[2] = 0u;
                a[3] = 0u;
            }
            uint32_t b[16][2];
#pragma unroll
            for (int np = 0; np < 8; np++) {
                uint32_t t4[4];
                ldsm_x4_t(t4, Whs + (kk * 16 + (lane & 15)) * BPITCH
                              + np * 16 + ((lane >> 4) << 3));
                b[np * 2][0] = t4[0]; b[np * 2][1] = t4[1];
                b[np * 2 + 1][0] = t4[2]; b[np * 2 + 1][1] = t4[3];
            }
#pragma unroll
            for (int nt = 0; nt < 16; nt++) mma_fp16(acc2[nt], a, b[nt]);
        }

#pragma unroll
        for (int rs = 0; rs < 2; rs++) {
            int rloc = rl + rs * 8;
            int node = m0 + (rloc >> 1);
            int b = b0g + (rloc & 1);
#pragma unroll
            for (int j = 0; j < 4; j++) {
                int col = j * 8 + cole;
                float gi0 = acc2[j][rs * 2],      gi1 = acc2[j][rs * 2 + 1];
                float gf0 = acc2[j + 4][rs * 2],  gf1 = acc2[j + 4][rs * 2 + 1];
                float go0 = acc2[j + 8][rs * 2],  go1 = acc2[j + 8][rs * 2 + 1];
                float gg0 = acc2[j + 12][rs * 2], gg1 = acc2[j + 12][rs * 2 + 1];

                float iv0 = fsig(gi0), iv1 = fsig(gi1);
                float fv0 = fsig(gf0), fv1 = fsig(gf1);
                float ov0 = fsig(go0), ov1 = fsig(go1);
                float gv0 = ftanh(gg0), gv1 = ftanh(gg1);

                int tslot = ((((cta * 4 + w) * 4 + mtile) * 2 + rs) * 4 + j) * 32 + lane;
                float2 cold = Cp[tslot];
                float cn0 = fv0 * cold.x + iv0 * gv0;
                float cn1 = fv1 * cold.y + iv1 * gv1;
                Cp[tslot] = make_float2(cn0, cn1);
                float h0 = ov0 * ftanh(cn0);
                float h1 = ov1 * ftanh(cn1);
                *(__half2*)&g_Rh[(size_t)node * 1024 + b * 32 + col] = __floats2half2_rn(h0, h1);
                if (t == Tt - 1)
                    *(float2*)&g_Hf[((size_t)node * 32 + b) * 32 + col] = make_float2(h0, h1);
            }
        }
    }
}

// ---------------------------------------------------------------------------
__global__ __launch_bounds__(256) void proj_kernel(const float* __restrict__ Wp,
                                                   const float* __restrict__ bp,
                                                   float* __restrict__ out) {
    int idx = blockIdx.x * 256 + threadIdx.x;
    int n = idx & (Nn - 1);
    int b = idx >> 11;
    float hv[32];
#pragma unroll
    for (int k = 0; k < 32; k++) hv[k] = g_Hf[(size_t)n * 1024 + b * 32 + k];
#pragma unroll
    for (int hz = 0; hz < HOR; hz++) {
        float s = bp[hz];
#pragma unroll
        for (int k = 0; k < 32; k++) s += hv[k] * Wp[k * HOR + hz];
        out[((size_t)b * HOR + hz) * Nn + n] = s;
    }
}

// ---------------------------------------------------------------------------
extern "C" void kernel_launch(void* const* d_in, const int* in_sizes, int n_in,
                              void* d_out, int out_size) {
    const float* x  = (const float*)d_in[0];
    const float* E1 = (const float*)d_in[1];
    const float* E2 = (const float*)d_in[2];
    const float* Wx = (const float*)d_in[3];
    const float* bx = (const float*)d_in[4];
    const float* Wh = (const float*)d_in[5];
    const float* bh = (const float*)d_in[6];
    const float* Wp = (const float*)d_in[7];
    const float* bp = (const float*)d_in[8];
    float* out = (float*)d_out;

    void *pRh, *pC, *pAh, *pGh, *pBxh;
    cudaGetSymbolAddress(&pRh, g_Rh);
    cudaGetSymbolAddress(&pC, g_C);
    cudaGetSymbolAddress(&pAh, g_Ah);
    cudaGetSymbolAddress(&pGh, g_Gh);
    cudaGetSymbolAddress(&pBxh, g_Bxh);

    static int smem_set = 0;
    if (!smem_set) {
        cudaFuncSetAttribute(sgemm_ksp, cudaFuncAttributeMaxDynamicSharedMemorySize,
                             KSP_SMEM);
        cudaFuncSetAttribute(fused_step, cudaFuncAttributeMaxDynamicSharedMemorySize,
                             FSMEM);
        smem_set = 1;
    }

    cudaMemsetAsync(pRh, 0, sizeof(__half) * Nn * 1024, 0);
    cudaMemsetAsync(pC, 0, sizeof(float) * Nn * Bb * Hh, 0);

    adj_kernel<<<Nn, 256>>>(E1, E2);
    buildx_kernel<<<(Nn * 1024) / 256, 256>>>(x);
    whs_prep<<<24, 256>>>(Wx, bx, Wh, bh);

    // Gx = A @ X_all (split-K prologue GEMM + sum)
    dim3 gxGrid(1024 / 128, Nn / 128, 2);
    sgemm_ksp<<<gxGrid, 128, KSP_SMEM>>>((const __half*)pAh, (const __half*)pBxh,
                                         (__half*)pGh);
    addx_kernel<<<GSTRIDE / 512, 256>>>();

    // recurrence: one fused launch per step
    dim3 fGrid(16, 16);
    for (int t = 0; t < Tt; t++) {
        fused_step<<<fGrid, 128, FSMEM>>>((const __half*)pAh, t);
    }

    proj_kernel<<<(Bb * Nn) / 256, 256>>>(Wp, bp, out);
}

// round 15
// speedup vs baseline: 1.1349x; 1.1349x over previous
#include <cuda_runtime.h>
#include <cuda_fp16.h>
#include <math.h>
#include <stdint.h>

// Problem constants
#define Nn   2048
#define CIN  2
#define Hh   32
#define EMB  16
#define HOR  12
#define Bb   32
#define Tt   16
#define KD   2048
#define GSTRIDE (Nn * 1024)
#define KSPLIT 1024

// Device scratch
__device__ __half g_Ah [Nn * Nn];       // adjacency fp16, [m][k] row-major
__device__ __half g_Rh [Nn * 1024];     // H fp16, [node(k)][b*32+h(n)]
__device__ __half g_Bxh[Nn * 1024];     // X all timesteps fp16
__device__ __half g_Gh [2 * GSTRIDE];   // split-K halves of A @ H, fp16
__device__ float  g_Gx [Nn * 1024];     // A @ X_all (summed, fp32)
__device__ float  g_C  [Nn * Bb * Hh];  // cell state, fragment-linear (lstm-private)
__device__ float  g_Hf [Nn * Bb * Hh];  // fp32 h (normal layout), written at t=15
__device__ __half g_Whsp[48 * 128];     // folded gate weights, packed fp16

// ---------------------------------------------------------------------------
__device__ __forceinline__ float fsig(float x) { return 1.0f / (1.0f + __expf(-x)); }
__device__ __forceinline__ float ftanh(float x) { return 2.0f / (1.0f + __expf(-2.0f * x)) - 1.0f; }

__device__ __forceinline__ void cp16(void* dst, const void* src) {
    uint32_t s = (uint32_t)__cvta_generic_to_shared(dst);
    asm volatile("cp.async.cg.shared.global [%0], [%1], 16;" :: "r"(s), "l"(src));
}
#define CP_COMMIT() asm volatile("cp.async.commit_group;" ::: "memory")
template <int N> __device__ __forceinline__ void cp_wait() {
    asm volatile("cp.async.wait_group %0;" :: "n"(N) : "memory");
}

__device__ __forceinline__ void ldsm_x4(uint32_t (&r)[4], const void* p) {
    uint32_t a = (uint32_t)__cvta_generic_to_shared(p);
    asm volatile("ldmatrix.sync.aligned.m8n8.x4.shared.b16 {%0,%1,%2,%3}, [%4];"
                 : "=r"(r[0]), "=r"(r[1]), "=r"(r[2]), "=r"(r[3]) : "r"(a));
}
__device__ __forceinline__ void ldsm_x4_t(uint32_t (&r)[4], const void* p) {
    uint32_t a = (uint32_t)__cvta_generic_to_shared(p);
    asm volatile("ldmatrix.sync.aligned.m8n8.x4.trans.shared.b16 {%0,%1,%2,%3}, [%4];"
                 : "=r"(r[0]), "=r"(r[1]), "=r"(r[2]), "=r"(r[3]) : "r"(a));
}
__device__ __forceinline__ void mma_fp16(float (&d)[4], const uint32_t (&a)[4], const uint32_t* b) {
    asm volatile(
        "mma.sync.aligned.m16n8k16.row.col.f32.f16.f16.f32 "
        "{%0,%1,%2,%3}, {%4,%5,%6,%7}, {%8,%9}, {%0,%1,%2,%3};"
        : "+f"(d[0]), "+f"(d[1]), "+f"(d[2]), "+f"(d[3])
        : "r"(a[0]), "r"(a[1]), "r"(a[2]), "r"(a[3]), "r"(b[0]), "r"(b[1]));
}

// ---------------------------------------------------------------------------
// A = softmax(relu(E1 @ E2^T)) row-major [m][k], fp16
// ---------------------------------------------------------------------------
__global__ __launch_bounds__(256) void adj_kernel(const float* __restrict__ E1,
                                                  const float* __restrict__ E2) {
    int r = blockIdx.x;
    int tid = threadIdx.x;
    __shared__ float e1[EMB];
    __shared__ float red[256];
    if (tid < EMB) e1[tid] = E1[r * EMB + tid];
    __syncthreads();

    float v[8];
    float mx = -1e30f;
#pragma unroll
    for (int i = 0; i < 8; i++) {
        int c = tid + i * 256;
        float d = 0.f;
#pragma unroll
        for (int e = 0; e < EMB; e++) d += e1[e] * E2[c * EMB + e];
        d = fmaxf(d, 0.f);
        v[i] = d;
        mx = fmaxf(mx, d);
    }
    red[tid] = mx; __syncthreads();
    for (int s = 128; s > 0; s >>= 1) {
        if (tid < s) red[tid] = fmaxf(red[tid], red[tid + s]);
        __syncthreads();
    }
    mx = red[0]; __syncthreads();

    float sum = 0.f;
#pragma unroll
    for (int i = 0; i < 8; i++) { v[i] = expf(v[i] - mx); sum += v[i]; }
    red[tid] = sum; __syncthreads();
    for (int s = 128; s > 0; s >>= 1) {
        if (tid < s) red[tid] += red[tid + s];
        __syncthreads();
    }
    float inv = 1.0f / red[0];
#pragma unroll
    for (int i = 0; i < 8; i++)
        g_Ah[(size_t)r * Nn + tid + i * 256] = __float2half_rn(v[i] * inv);
}

// ---------------------------------------------------------------------------
__global__ __launch_bounds__(256) void buildx_kernel(const float* __restrict__ x) {
    int idx = blockIdx.x * 256 + threadIdx.x;
    int n = idx >> 10;
    int q = idx & 1023;
    int t = q >> 6;
    int r6 = q & 63;
    int b = r6 >> 1;
    int c = r6 & 1;
    g_Bxh[idx] = __float2half_rn(x[(((size_t)b * Tt + t) * Nn + n) * CIN + c]);
}

// folded gate weights -> packed fp16 global (once)
__global__ __launch_bounds__(256) void whs_prep(const float* __restrict__ Wx,
                                                const float* __restrict__ bx,
                                                const float* __restrict__ Wh,
                                                const float* __restrict__ bh) {
    int i = blockIdx.x * 256 + threadIdx.x;
    int k = i >> 7, g = i & 127;
    float v;
    if (k < 32)       v = Wh[k * 128 + g];
    else if (k == 32) v = Wx[g];
    else if (k == 33) v = Wx[128 + g];
    else if (k == 34) v = bx[g] + bh[g];
    else              v = 0.f;
    g_Whsp[i] = __float2half_rn(v);
}

// g_Gx = (fp32) g_Gh[0..] + g_Gh[GSTRIDE..]
__global__ __launch_bounds__(256) void addx_kernel() {
    int i = blockIdx.x * 256 + threadIdx.x;
    __half2 a = ((const __half2*)g_Gh)[i];
    __half2 b = ((const __half2*)(g_Gh + GSTRIDE))[i];
    ((float2*)g_Gx)[i] = make_float2(__low2float(a) + __low2float(b),
                                     __high2float(a) + __high2float(b));
}

// ---------------------------------------------------------------------------
// fp16 tensor-core GEMM, split-K, BK=64, 3-stage cp.async pipeline
// 128 threads (4 warps, 64x64 tiles), 2 CTAs/SM. Halved barrier count vs BK=32.
// ---------------------------------------------------------------------------
#define APITCH2 72                      // 64 + 8 skew halves
#define BPITCH 136                      // 128 + 8 skew halves
#define ASZ2 (128 * APITCH2)            // 9216 halves
#define BSZ2 (64 * BPITCH)              // 8704 halves
#define STG2 (ASZ2 + BSZ2)              // 17920 halves = 35840 B
#define GEMM_SMEM (3 * STG2 * (int)sizeof(__half))   // 107520 B

__global__ void __launch_bounds__(128, 2)
sgemm_fp16(const __half* __restrict__ Ah, const __half* __restrict__ Bh,
           __half* __restrict__ C) {
    extern __shared__ __half smem[];
    int tid = threadIdx.x;
    int lane = tid & 31;
    int w = tid >> 5;
    int bm0 = blockIdx.y * 128;
    int bn0 = blockIdx.x * 128;
    int kBase = blockIdx.z * KSPLIT;
    C += (size_t)blockIdx.z * GSTRIDE;
    int wm0 = (w & 1) * 64;
    int wn0 = (w >> 1) * 64;

    float acc[4][8][4];
#pragma unroll
    for (int mt = 0; mt < 4; mt++)
#pragma unroll
        for (int nt = 0; nt < 8; nt++)
#pragma unroll
            for (int i = 0; i < 4; i++) acc[mt][nt][i] = 0.f;

    auto load_stage = [&](int s, int k0) {
        __half* sA = smem + (s % 3) * STG2;
        __half* sB = sA + ASZ2;
        // A: 128 rows x 64 k halves = 1024 16B-chunks
#pragma unroll
        for (int i = 0; i < 8; i++) {
            int ch = tid + i * 128;
            int r = ch >> 3;
            int c = ch & 7;
            cp16(sA + r * APITCH2 + c * 8,
                 Ah + (size_t)(bm0 + r) * KD + kBase + k0 + c * 8);
        }
        // B: 64 k-rows x 128 n halves = 1024 chunks
#pragma unroll
        for (int i = 0; i < 8; i++) {
            int ch = tid + i * 128;
            int r = ch >> 4;
            int c = ch & 15;
            cp16(sB + r * BPITCH + c * 8,
                 Bh + (size_t)(kBase + k0 + r) * 1024 + bn0 + c * 8);
        }
    };

    load_stage(0, 0);  CP_COMMIT();
    load_stage(1, 64); CP_COMMIT();

    const int NIT = KSPLIT / 64;   // 16
    for (int it = 0; it < NIT; ++it) {
        if (it + 2 < NIT) cp_wait<1>(); else cp_wait<0>();
        __syncthreads();
        if (it + 2 < NIT) {
            load_stage(it + 2, (it + 2) * 64);
            CP_COMMIT();
        }

        const __half* sA = smem + (it % 3) * STG2;
        const __half* sB = sA + ASZ2;
#pragma unroll
        for (int kk = 0; kk < 4; kk++) {
            uint32_t a[4][4];
#pragma unroll
            for (int mt = 0; mt < 4; mt++) {
                ldsm_x4(a[mt], sA + (wm0 + mt * 16 + (lane & 15)) * APITCH2
                               + kk * 16 + ((lane >> 4) << 3));
            }
            uint32_t b[8][2];
#pragma unroll
            for (int np = 0; np < 4; np++) {
                uint32_t t4[4];
                ldsm_x4_t(t4, sB + (kk * 16 + (lane & 15)) * BPITCH
                              + wn0 + np * 16 + ((lane >> 4) << 3));
                b[np * 2][0] = t4[0]; b[np * 2][1] = t4[1];
                b[np * 2 + 1][0] = t4[2]; b[np * 2 + 1][1] = t4[3];
            }
#pragma unroll
            for (int mt = 0; mt < 4; mt++)
#pragma unroll
                for (int nt = 0; nt < 8; nt++) mma_fp16(acc[mt][nt], a[mt], b[nt]);
        }
        __syncthreads();
    }

#pragma unroll
    for (int mt = 0; mt < 4; mt++) {
        int r0 = bm0 + wm0 + mt * 16 + (lane >> 2);
#pragma unroll
        for (int nt = 0; nt < 8; nt++) {
            int c0 = bn0 + wn0 + nt * 8 + 2 * (lane & 3);
            *(__half2*)&C[(size_t)r0 * 1024 + c0] = __floats2half2_rn(acc[mt][nt][0], acc[mt][nt][1]);
            *(__half2*)&C[(size_t)(r0 + 8) * 1024 + c0] = __floats2half2_rn(acc[mt][nt][2], acc[mt][nt][3]);
        }
    }
}

// ---------------------------------------------------------------------------
// LSTM (k=48 folded gates): smem-staged G + cp.async Whs from packed global
// (unchanged from R12 — known-good)
// ---------------------------------------------------------------------------
#define APITCH 40
__global__ void __launch_bounds__(256, 2)
lstm_tc(int t) {
    __shared__ __half Whs[48 * BPITCH];
    __shared__ __half Gs0[128 * APITCH];
    __shared__ __half Gs1[128 * APITCH];
    int tid = threadIdx.x;
    int rbase = blockIdx.x * 128;

#pragma unroll
    for (int i = 0; i < 2; i++) {
        int ch = tid + i * 256;
        int r = ch >> 2, c = ch & 3;
        cp16(Gs0 + r * APITCH + c * 8, g_Gh + (size_t)(rbase + r) * 32 + c * 8);
        cp16(Gs1 + r * APITCH + c * 8, g_Gh + GSTRIDE + (size_t)(rbase + r) * 32 + c * 8);
    }
#pragma unroll
    for (int i = 0; i < 3; i++) {
        int ch = tid + i * 256;
        int r = ch >> 4, c = ch & 15;
        cp16(Whs + r * BPITCH + c * 8, g_Whsp + r * 128 + c * 8);
    }
    CP_COMMIT();
    cp_wait<0>();
    __syncthreads();

    int lane = tid & 31, warp = tid >> 5;
    int wrow = warp * 16;
    int r_lo = rbase + wrow + (lane >> 2);

    int n0 = r_lo >> 5, b0 = r_lo & 31;
    int r_hi = r_lo + 8;
    int n1 = r_hi >> 5, b1 = r_hi & 31;
    float2 axlo = *(const float2*)&g_Gx[(size_t)n0 * 1024 + t * 64 + b0 * 2];
    float2 axhi = *(const float2*)&g_Gx[(size_t)n1 * 1024 + t * 64 + b1 * 2];

    float acc[16][4];
#pragma unroll
    for (int nt = 0; nt < 16; nt++)
#pragma unroll
        for (int i = 0; i < 4; i++) acc[nt][i] = 0.f;

#pragma unroll
    for (int kk = 0; kk < 3; kk++) {
        uint32_t a[4];
        if (kk < 2) {
            uint32_t a0[4], a1[4];
            const __half* p0 = Gs0 + (wrow + (lane & 15)) * APITCH + kk * 16 + ((lane >> 4) << 3);
            const __half* p1 = Gs1 + (wrow + (lane & 15)) * APITCH + kk * 16 + ((lane >> 4) << 3);
            ldsm_x4(a0, p0);
            ldsm_x4(a1, p1);
#pragma unroll
            for (int i = 0; i < 4; i++) {
                __half2 ssum = __hadd2(*reinterpret_cast<__half2*>(&a0[i]),
                                       *reinterpret_cast<__half2*>(&a1[i]));
                a[i] = *reinterpret_cast<uint32_t*>(&ssum);
            }
        } else {
            int sel = lane & 3;
            __half2 hlo = __floats2half2_rn(axlo.x, axlo.y);
            __half2 hhi = __floats2half2_rn(axhi.x, axhi.y);
            __half2 one = __floats2half2_rn(1.0f, 0.0f);
            uint32_t ulo = *reinterpret_cast<uint32_t*>(&hlo);
            uint32_t uhi = *reinterpret_cast<uint32_t*>(&hhi);
            uint32_t uon = *reinterpret_cast<uint32_t*>(&one);
            a[0] = (sel == 0) ? ulo : ((sel == 1) ? uon : 0u);
            a[1] = (sel == 0) ? uhi : ((sel == 1) ? uon : 0u);
            a[2] = 0u;
            a[3] = 0u;
        }
        uint32_t b[16][2];
#pragma unroll
        for (int np = 0; np < 8; np++) {
            uint32_t t4[4];
            ldsm_x4_t(t4, Whs + (kk * 16 + (lane & 15)) * BPITCH + np * 16 + ((lane >> 4) << 3));
            b[np * 2][0] = t4[0]; b[np * 2][1] = t4[1];
            b[np * 2 + 1][0] = t4[2]; b[np * 2 + 1][1] = t4[3];
        }
#pragma unroll
        for (int nt = 0; nt < 16; nt++) mma_fp16(acc[nt], a, b[nt]);
    }

    int cole = 2 * (lane & 3);
    float2* Cp = (float2*)g_C;
#pragma unroll
    for (int rs = 0; rs < 2; rs++) {
        int r = r_lo + rs * 8;
#pragma unroll
        for (int j = 0; j < 4; j++) {
            int col = j * 8 + cole;
            float gi0 = acc[j][rs * 2],      gi1 = acc[j][rs * 2 + 1];
            float gf0 = acc[j + 4][rs * 2],  gf1 = acc[j + 4][rs * 2 + 1];
            float go0 = acc[j + 8][rs * 2],  go1 = acc[j + 8][rs * 2 + 1];
            float gg0 = acc[j + 12][rs * 2], gg1 = acc[j + 12][rs * 2 + 1];

            float iv0 = fsig(gi0), iv1 = fsig(gi1);
            float fv0 = fsig(gf0), fv1 = fsig(gf1);
            float ov0 = fsig(go0), ov1 = fsig(go1);
            float gv0 = ftanh(gg0), gv1 = ftanh(gg1);

            int tslot = ((((blockIdx.x * 8 + warp) * 2 + rs) * 4 + j) << 5) + lane;
            float2 cold = Cp[tslot];
            float cn0 = fv0 * cold.x + iv0 * gv0;
            float cn1 = fv1 * cold.y + iv1 * gv1;
            Cp[tslot] = make_float2(cn0, cn1);
            float h0 = ov0 * ftanh(cn0);
            float h1 = ov1 * ftanh(cn1);
            *(__half2*)&g_Rh[(size_t)r * 32 + col] = __floats2half2_rn(h0, h1);
            if (t == Tt - 1) *(float2*)&g_Hf[(size_t)r * 32 + col] = make_float2(h0, h1);
        }
    }
}

// ---------------------------------------------------------------------------
__global__ __launch_bounds__(256) void proj_kernel(const float* __restrict__ Wp,
                                                   const float* __restrict__ bp,
                                                   float* __restrict__ out) {
    int idx = blockIdx.x * 256 + threadIdx.x;
    int n = idx & (Nn - 1);
    int b = idx >> 11;
    float hv[32];
#pragma unroll
    for (int k = 0; k < 32; k++) hv[k] = g_Hf[(size_t)n * 1024 + b * 32 + k];
#pragma unroll
    for (int hz = 0; hz < HOR; hz++) {
        float s = bp[hz];
#pragma unroll
        for (int k = 0; k < 32; k++) s += hv[k] * Wp[k * HOR + hz];
        out[((size_t)b * HOR + hz) * Nn + n] = s;
    }
}

// ---------------------------------------------------------------------------
extern "C" void kernel_launch(void* const* d_in, const int* in_sizes, int n_in,
                              void* d_out, int out_size) {
    const float* x  = (const float*)d_in[0];
    const float* E1 = (const float*)d_in[1];
    const float* E2 = (const float*)d_in[2];
    const float* Wx = (const float*)d_in[3];
    const float* bx = (const float*)d_in[4];
    const float* Wh = (const float*)d_in[5];
    const float* bh = (const float*)d_in[6];
    const float* Wp = (const float*)d_in[7];
    const float* bp = (const float*)d_in[8];
    float* out = (float*)d_out;

    void *pRh, *pC, *pAh, *pGh, *pBxh;
    cudaGetSymbolAddress(&pRh, g_Rh);
    cudaGetSymbolAddress(&pC, g_C);
    cudaGetSymbolAddress(&pAh, g_Ah);
    cudaGetSymbolAddress(&pGh, g_Gh);
    cudaGetSymbolAddress(&pBxh, g_Bxh);

    static int smem_set = 0;
    if (!smem_set) {
        cudaFuncSetAttribute(sgemm_fp16, cudaFuncAttributeMaxDynamicSharedMemorySize,
                             GEMM_SMEM);
        smem_set = 1;
    }

    cudaMemsetAsync(pRh, 0, sizeof(__half) * Nn * 1024, 0);
    cudaMemsetAsync(pC, 0, sizeof(float) * Nn * Bb * Hh, 0);

    adj_kernel<<<Nn, 256>>>(E1, E2);
    buildx_kernel<<<(Nn * 1024) / 256, 256>>>(x);
    whs_prep<<<24, 256>>>(Wx, bx, Wh, bh);

    dim3 gemmGrid(1024 / 128, Nn / 128, 2);  // (8, 16, 2)

    // Gx = A @ X_all
    sgemm_fp16<<<gemmGrid, 128, GEMM_SMEM>>>((const __half*)pAh, (const __half*)pBxh,
                                             (__half*)pGh);
    addx_kernel<<<GSTRIDE / 512, 256>>>();

    for (int t = 0; t < Tt; t++) {
        sgemm_fp16<<<gemmGrid, 128, GEMM_SMEM>>>((const __half*)pAh, (const __half*)pRh,
                                                 (__half*)pGh);
        lstm_tc<<<(Nn * Bb) / 128, 256>>>(t);
    }

    proj_kernel<<<(Bb * Nn) / 256, 256>>>(Wp, bp, out);
}

// round 16
// speedup vs baseline: 1.2832x; 1.1307x over previous
#include <cuda_runtime.h>
#include <cuda_fp16.h>
#include <math.h>
#include <stdint.h>

// Problem constants
#define Nn   2048
#define CIN  2
#define Hh   32
#define EMB  16
#define HOR  12
#define Bb   32
#define Tt   16
#define KD   2048
#define GSTRIDE (Nn * 1024)
#define KSPLIT 1024

// Device scratch
__device__ __half g_Ah [Nn * Nn];       // adjacency fp16, [m][k] row-major
__device__ __half g_Rh [Nn * 1024];     // H fp16, [node(k)][b*32+h(n)]
__device__ __half g_Bxh[Nn * 1024];     // X all timesteps fp16
__device__ __half g_Gh [2 * GSTRIDE];   // split-K halves of A @ H, fp16
__device__ float  g_Gx [Nn * 1024];     // A @ X_all (summed, fp32)
__device__ float  g_C  [Nn * Bb * Hh];  // cell state, fragment-linear (lstm-private)
__device__ float  g_Hf [Nn * Bb * Hh];  // fp32 h [(n*32+b)*32+h], written at t=15
__device__ __half g_Whsp[48 * 128];     // folded gate weights, packed fp16

// ---------------------------------------------------------------------------
__device__ __forceinline__ float fsig(float x) { return 1.0f / (1.0f + __expf(-x)); }
__device__ __forceinline__ float ftanh(float x) { return 2.0f / (1.0f + __expf(-2.0f * x)) - 1.0f; }

__device__ __forceinline__ void cp16(void* dst, const void* src) {
    uint32_t s = (uint32_t)__cvta_generic_to_shared(dst);
    asm volatile("cp.async.cg.shared.global [%0], [%1], 16;" :: "r"(s), "l"(src));
}
#define CP_COMMIT() asm volatile("cp.async.commit_group;" ::: "memory")
template <int N> __device__ __forceinline__ void cp_wait() {
    asm volatile("cp.async.wait_group %0;" :: "n"(N) : "memory");
}

__device__ __forceinline__ void ldsm_x4(uint32_t (&r)[4], const void* p) {
    uint32_t a = (uint32_t)__cvta_generic_to_shared(p);
    asm volatile("ldmatrix.sync.aligned.m8n8.x4.shared.b16 {%0,%1,%2,%3}, [%4];"
                 : "=r"(r[0]), "=r"(r[1]), "=r"(r[2]), "=r"(r[3]) : "r"(a));
}
__device__ __forceinline__ void ldsm_x4_t(uint32_t (&r)[4], const void* p) {
    uint32_t a = (uint32_t)__cvta_generic_to_shared(p);
    asm volatile("ldmatrix.sync.aligned.m8n8.x4.trans.shared.b16 {%0,%1,%2,%3}, [%4];"
                 : "=r"(r[0]), "=r"(r[1]), "=r"(r[2]), "=r"(r[3]) : "r"(a));
}
__device__ __forceinline__ void mma_fp16(float (&d)[4], const uint32_t (&a)[4], const uint32_t* b) {
    asm volatile(
        "mma.sync.aligned.m16n8k16.row.col.f32.f16.f16.f32 "
        "{%0,%1,%2,%3}, {%4,%5,%6,%7}, {%8,%9}, {%0,%1,%2,%3};"
        : "+f"(d[0]), "+f"(d[1]), "+f"(d[2]), "+f"(d[3])
        : "r"(a[0]), "r"(a[1]), "r"(a[2]), "r"(a[3]), "r"(b[0]), "r"(b[1]));
}

// ---------------------------------------------------------------------------
// A = softmax(relu(E1 @ E2^T)) row-major [m][k], fp16
// ---------------------------------------------------------------------------
__global__ __launch_bounds__(256) void adj_kernel(const float* __restrict__ E1,
                                                  const float* __restrict__ E2) {
    int r = blockIdx.x;
    int tid = threadIdx.x;
    __shared__ float e1[EMB];
    __shared__ float red[256];
    if (tid < EMB) e1[tid] = E1[r * EMB + tid];
    __syncthreads();

    float v[8];
    float mx = -1e30f;
#pragma unroll
    for (int i = 0; i < 8; i++) {
        int c = tid + i * 256;
        float d = 0.f;
#pragma unroll
        for (int e = 0; e < EMB; e++) d += e1[e] * E2[c * EMB + e];
        d = fmaxf(d, 0.f);
        v[i] = d;
        mx = fmaxf(mx, d);
    }
    red[tid] = mx; __syncthreads();
    for (int s = 128; s > 0; s >>= 1) {
        if (tid < s) red[tid] = fmaxf(red[tid], red[tid + s]);
        __syncthreads();
    }
    mx = red[0]; __syncthreads();

    float sum = 0.f;
#pragma unroll
    for (int i = 0; i < 8; i++) { v[i] = expf(v[i] - mx); sum += v[i]; }
    red[tid] = sum; __syncthreads();
    for (int s = 128; s > 0; s >>= 1) {
        if (tid < s) red[tid] += red[tid + s];
        __syncthreads();
    }
    float inv = 1.0f / red[0];
#pragma unroll
    for (int i = 0; i < 8; i++)
        g_Ah[(size_t)r * Nn + tid + i * 256] = __float2half_rn(v[i] * inv);
}

// ---------------------------------------------------------------------------
__global__ __launch_bounds__(256) void buildx_kernel(const float* __restrict__ x) {
    int idx = blockIdx.x * 256 + threadIdx.x;
    int n = idx >> 10;
    int q = idx & 1023;
    int t = q >> 6;
    int r6 = q & 63;
    int b = r6 >> 1;
    int c = r6 & 1;
    g_Bxh[idx] = __float2half_rn(x[(((size_t)b * Tt + t) * Nn + n) * CIN + c]);
}

// folded gate weights -> packed fp16 global (once)
__global__ __launch_bounds__(256) void whs_prep(const float* __restrict__ Wx,
                                                const float* __restrict__ bx,
                                                const float* __restrict__ Wh,
                                                const float* __restrict__ bh) {
    int i = blockIdx.x * 256 + threadIdx.x;
    int k = i >> 7, g = i & 127;
    float v;
    if (k < 32)       v = Wh[k * 128 + g];
    else if (k == 32) v = Wx[g];
    else if (k == 33) v = Wx[128 + g];
    else if (k == 34) v = bx[g] + bh[g];
    else              v = 0.f;
    g_Whsp[i] = __float2half_rn(v);
}

// g_Gx = (fp32) g_Gh[0..] + g_Gh[GSTRIDE..]
__global__ __launch_bounds__(256) void addx_kernel() {
    int i = blockIdx.x * 256 + threadIdx.x;
    __half2 a = ((const __half2*)g_Gh)[i];
    __half2 b = ((const __half2*)(g_Gh + GSTRIDE))[i];
    ((float2*)g_Gx)[i] = make_float2(__low2float(a) + __low2float(b),
                                     __high2float(a) + __high2float(b));
}

// ---------------------------------------------------------------------------
// fp16 tensor-core GEMM, split-K, BK=32, 4-stage pipeline (R12 exact config).
// gridDim.x selects n-tiles over the caller-provided B/C base pointers.
// ---------------------------------------------------------------------------
#define APITCH 40
#define BPITCH 136
#define ASZH (128 * APITCH)
#define BSZH (32 * BPITCH)
#define SSTAGEH (ASZH + BSZH)       // 9472 halves
#define GEMM_SMEM (4 * SSTAGEH * (int)sizeof(__half))   // 75776 B

__global__ void __launch_bounds__(128, 2)
sgemm_fp16(const __half* __restrict__ Ah, const __half* __restrict__ Bh,
           __half* __restrict__ C) {
    extern __shared__ __half smem[];
    int tid = threadIdx.x;
    int lane = tid & 31;
    int w = tid >> 5;
    int bm0 = blockIdx.y * 128;
    int bn0 = blockIdx.x * 128;
    int kBase = blockIdx.z * KSPLIT;
    C += (size_t)blockIdx.z * GSTRIDE;
    int wm0 = (w & 1) * 64;
    int wn0 = (w >> 1) * 64;

    float acc[4][8][4];
#pragma unroll
    for (int mt = 0; mt < 4; mt++)
#pragma unroll
        for (int nt = 0; nt < 8; nt++)
#pragma unroll
            for (int i = 0; i < 4; i++) acc[mt][nt][i] = 0.f;

    auto load_stage = [&](int s, int k0) {
        __half* sA = smem + (s & 3) * SSTAGEH;
        __half* sB = sA + ASZH;
#pragma unroll
        for (int i = 0; i < 4; i++) {
            int ch = tid + i * 128;
            int r = ch >> 2;
            int c = ch & 3;
            cp16(sA + r * APITCH + c * 8,
                 Ah + (size_t)(bm0 + r) * KD + kBase + k0 + c * 8);
        }
#pragma unroll
        for (int i = 0; i < 4; i++) {
            int ch = tid + i * 128;
            int r = ch >> 4;
            int c = ch & 15;
            cp16(sB + r * BPITCH + c * 8,
                 Bh + (size_t)(kBase + k0 + r) * 1024 + bn0 + c * 8);
        }
    };

    load_stage(0, 0);  CP_COMMIT();
    load_stage(1, 32); CP_COMMIT();
    load_stage(2, 64); CP_COMMIT();

    const int NIT = KSPLIT / 32;   // 32
    for (int it = 0; it < NIT; ++it) {
        if (it + 2 < NIT)      cp_wait<2>();
        else if (it + 1 < NIT) cp_wait<1>();
        else                   cp_wait<0>();
        __syncthreads();
        if (it + 3 < NIT) {
            load_stage(it + 3, (it + 3) * 32);
            CP_COMMIT();
        }

        const __half* sA = smem + (it & 3) * SSTAGEH;
        const __half* sB = sA + ASZH;
#pragma unroll
        for (int kk = 0; kk < 2; kk++) {
            uint32_t a[4][4];
#pragma unroll
            for (int mt = 0; mt < 4; mt++) {
                ldsm_x4(a[mt], sA + (wm0 + mt * 16 + (lane & 15)) * APITCH
                               + kk * 16 + ((lane >> 4) << 3));
            }
            uint32_t b[8][2];
#pragma unroll
            for (int np = 0; np < 4; np++) {
                uint32_t t4[4];
                ldsm_x4_t(t4, sB + (kk * 16 + (lane & 15)) * BPITCH
                              + wn0 + np * 16 + ((lane >> 4) << 3));
                b[np * 2][0] = t4[0]; b[np * 2][1] = t4[1];
                b[np * 2 + 1][0] = t4[2]; b[np * 2 + 1][1] = t4[3];
            }
#pragma unroll
            for (int mt = 0; mt < 4; mt++)
#pragma unroll
                for (int nt = 0; nt < 8; nt++) mma_fp16(acc[mt][nt], a[mt], b[nt]);
        }
        __syncthreads();
    }

#pragma unroll
    for (int mt = 0; mt < 4; mt++) {
        int r0 = bm0 + wm0 + mt * 16 + (lane >> 2);
#pragma unroll
        for (int nt = 0; nt < 8; nt++) {
            int c0 = bn0 + wn0 + nt * 8 + 2 * (lane & 3);
            *(__half2*)&C[(size_t)r0 * 1024 + c0] = __floats2half2_rn(acc[mt][nt][0], acc[mt][nt][1]);
            *(__half2*)&C[(size_t)(r0 + 8) * 1024 + c0] = __floats2half2_rn(acc[mt][nt][2], acc[mt][nt][3]);
        }
    }
}

// ---------------------------------------------------------------------------
// LSTM for one batch half (gbh = 0/1): rows (node, b) with b in [gbh*16, +16).
// CTA covers 8 nodes x 16 batches = 128 lstm rows. Grid = 256 CTAs.
// ---------------------------------------------------------------------------
__global__ void __launch_bounds__(256, 2)
lstm_half(int t, int gbh) {
    __shared__ __half Whs[48 * BPITCH];
    __shared__ __half Gs0[128 * APITCH];
    __shared__ __half Gs1[128 * APITCH];
    int tid = threadIdx.x;
    int node0 = blockIdx.x * 8;
    size_t base = (size_t)node0 * 1024 + gbh * 512;

    // stage both G halves: row r = node_l*16 + b_l -> contiguous 32h per row
#pragma unroll
    for (int i = 0; i < 2; i++) {
        int ch = tid + i * 256;
        int r = ch >> 2, c = ch & 3;
        int node_l = r >> 4, b_l = r & 15;
        size_t src = base + (size_t)node_l * 1024 + b_l * 32 + c * 8;
        cp16(Gs0 + r * APITCH + c * 8, g_Gh + src);
        cp16(Gs1 + r * APITCH + c * 8, g_Gh + GSTRIDE + src);
    }
#pragma unroll
    for (int i = 0; i < 3; i++) {
        int ch = tid + i * 256;
        int r = ch >> 4, c = ch & 15;
        cp16(Whs + r * BPITCH + c * 8, g_Whsp + r * 128 + c * 8);
    }
    CP_COMMIT();
    cp_wait<0>();
    __syncthreads();

    int lane = tid & 31, warp = tid >> 5;
    int wrow = warp * 16;
    int r_lo = wrow + (lane >> 2);          // local row 0..127 (b_l = r&15 in 0..7)
    int node = node0 + (r_lo >> 4);
    int b_lo = gbh * 16 + (r_lo & 15);
    int b_hi = b_lo + 8;                    // r_hi = r_lo + 8: same node, b_l+8

    float2 axlo = *(const float2*)&g_Gx[(size_t)node * 1024 + t * 64 + b_lo * 2];
    float2 axhi = *(const float2*)&g_Gx[(size_t)node * 1024 + t * 64 + b_hi * 2];

    float acc[16][4];
#pragma unroll
    for (int nt = 0; nt < 16; nt++)
#pragma unroll
        for (int i = 0; i < 4; i++) acc[nt][i] = 0.f;

#pragma unroll
    for (int kk = 0; kk < 3; kk++) {
        uint32_t a[4];
        if (kk < 2) {
            uint32_t a0[4], a1[4];
            const __half* p0 = Gs0 + (wrow + (lane & 15)) * APITCH + kk * 16 + ((lane >> 4) << 3);
            const __half* p1 = Gs1 + (wrow + (lane & 15)) * APITCH + kk * 16 + ((lane >> 4) << 3);
            ldsm_x4(a0, p0);
            ldsm_x4(a1, p1);
#pragma unroll
            for (int i = 0; i < 4; i++) {
                __half2 ssum = __hadd2(*reinterpret_cast<__half2*>(&a0[i]),
                                       *reinterpret_cast<__half2*>(&a1[i]));
                a[i] = *reinterpret_cast<uint32_t*>(&ssum);
            }
        } else {
            int sel = lane & 3;
            __half2 hlo = __floats2half2_rn(axlo.x, axlo.y);
            __half2 hhi = __floats2half2_rn(axhi.x, axhi.y);
            __half2 one = __floats2half2_rn(1.0f, 0.0f);
            uint32_t ulo = *reinterpret_cast<uint32_t*>(&hlo);
            uint32_t uhi = *reinterpret_cast<uint32_t*>(&hhi);
            uint32_t uon = *reinterpret_cast<uint32_t*>(&one);
            a[0] = (sel == 0) ? ulo : ((sel == 1) ? uon : 0u);
            a[1] = (sel == 0) ? uhi : ((sel == 1) ? uon : 0u);
            a[2] = 0u;
            a[3] = 0u;
        }
        uint32_t b[16][2];
#pragma unroll
        for (int np = 0; np < 8; np++) {
            uint32_t t4[4];
            ldsm_x4_t(t4, Whs + (kk * 16 + (lane & 15)) * BPITCH + np * 16 + ((lane >> 4) << 3));
            b[np * 2][0] = t4[0]; b[np * 2][1] = t4[1];
            b[np * 2 + 1][0] = t4[2]; b[np * 2 + 1][1] = t4[3];
        }
#pragma unroll
        for (int nt = 0; nt < 16; nt++) mma_fp16(acc[nt], a, b[nt]);
    }

    int cole = 2 * (lane & 3);
    float2* Cp = (float2*)g_C;
#pragma unroll
    for (int rs = 0; rs < 2; rs++) {
        int b = gbh * 16 + ((r_lo + rs * 8) & 15);
        size_t rglob = (size_t)node * 32 + b;
#pragma unroll
        for (int j = 0; j < 4; j++) {
            int col = j * 8 + cole;
            float gi0 = acc[j][rs * 2],      gi1 = acc[j][rs * 2 + 1];
            float gf0 = acc[j + 4][rs * 2],  gf1 = acc[j + 4][rs * 2 + 1];
            float go0 = acc[j + 8][rs * 2],  go1 = acc[j + 8][rs * 2 + 1];
            float gg0 = acc[j + 12][rs * 2], gg1 = acc[j + 12][rs * 2 + 1];

            float iv0 = fsig(gi0), iv1 = fsig(gi1);
            float fv0 = fsig(gf0), fv1 = fsig(gf1);
            float ov0 = fsig(go0), ov1 = fsig(go1);
            float gv0 = ftanh(gg0), gv1 = ftanh(gg1);

            int tslot = ((((((gbh * 256 + blockIdx.x) * 8 + warp) * 2 + rs) * 4 + j)) << 5) + lane;
            float2 cold = Cp[tslot];
            float cn0 = fv0 * cold.x + iv0 * gv0;
            float cn1 = fv1 * cold.y + iv1 * gv1;
            Cp[tslot] = make_float2(cn0, cn1);
            float h0 = ov0 * ftanh(cn0);
            float h1 = ov1 * ftanh(cn1);
            *(__half2*)&g_Rh[(size_t)node * 1024 + b * 32 + col] = __floats2half2_rn(h0, h1);
            if (t == Tt - 1) *(float2*)&g_Hf[rglob * 32 + col] = make_float2(h0, h1);
        }
    }
}

// ---------------------------------------------------------------------------
__global__ __launch_bounds__(256) void proj_kernel(const float* __restrict__ Wp,
                                                   const float* __restrict__ bp,
                                                   float* __restrict__ out) {
    int idx = blockIdx.x * 256 + threadIdx.x;
    int n = idx & (Nn - 1);
    int b = idx >> 11;
    float hv[32];
#pragma unroll
    for (int k = 0; k < 32; k++) hv[k] = g_Hf[(size_t)n * 1024 + b * 32 + k];
#pragma unroll
    for (int hz = 0; hz < HOR; hz++) {
        float s = bp[hz];
#pragma unroll
        for (int k = 0; k < 32; k++) s += hv[k] * Wp[k * HOR + hz];
        out[((size_t)b * HOR + hz) * Nn + n] = s;
    }
}

// ---------------------------------------------------------------------------
extern "C" void kernel_launch(void* const* d_in, const int* in_sizes, int n_in,
                              void* d_out, int out_size) {
    const float* x  = (const float*)d_in[0];
    const float* E1 = (const float*)d_in[1];
    const float* E2 = (const float*)d_in[2];
    const float* Wx = (const float*)d_in[3];
    const float* bx = (const float*)d_in[4];
    const float* Wh = (const float*)d_in[5];
    const float* bh = (const float*)d_in[6];
    const float* Wp = (const float*)d_in[7];
    const float* bp = (const float*)d_in[8];
    float* out = (float*)d_out;

    void *pRh, *pC, *pAh, *pGh, *pBxh;
    cudaGetSymbolAddress(&pRh, g_Rh);
    cudaGetSymbolAddress(&pC, g_C);
    cudaGetSymbolAddress(&pAh, g_Ah);
    cudaGetSymbolAddress(&pGh, g_Gh);
    cudaGetSymbolAddress(&pBxh, g_Bxh);

    static cudaStream_t s1 = 0, s2 = 0;
    static cudaEvent_t evRoot = 0, ev1 = 0, ev2 = 0;
    static int init_done = 0;
    if (!init_done) {
        cudaFuncSetAttribute(sgemm_fp16, cudaFuncAttributeMaxDynamicSharedMemorySize,
                             GEMM_SMEM);
        cudaStreamCreateWithFlags(&s1, cudaStreamNonBlocking);
        cudaStreamCreateWithFlags(&s2, cudaStreamNonBlocking);
        cudaEventCreateWithFlags(&evRoot, cudaEventDisableTiming);
        cudaEventCreateWithFlags(&ev1, cudaEventDisableTiming);
        cudaEventCreateWithFlags(&ev2, cudaEventDisableTiming);
        init_done = 1;
    }

    cudaMemsetAsync(pRh, 0, sizeof(__half) * Nn * 1024, 0);
    cudaMemsetAsync(pC, 0, sizeof(float) * Nn * Bb * Hh, 0);

    adj_kernel<<<Nn, 256>>>(E1, E2);
    buildx_kernel<<<(Nn * 1024) / 256, 256>>>(x);
    whs_prep<<<24, 256>>>(Wx, bx, Wh, bh);

    // Gx = A @ X_all (full width) on default stream
    dim3 gxGrid(8, 16, 2);
    sgemm_fp16<<<gxGrid, 128, GEMM_SMEM>>>((const __half*)pAh, (const __half*)pBxh,
                                           (__half*)pGh);
    addx_kernel<<<GSTRIDE / 512, 256>>>();

    // fork two independent batch-half pipelines
    cudaEventRecord(evRoot, 0);
    cudaStreamWaitEvent(s1, evRoot, 0);
    cudaStreamWaitEvent(s2, evRoot, 0);

    dim3 hGrid(4, 16, 2);   // 128 CTAs per half (N=512)
    const __half* Ah = (const __half*)pAh;
    __half* Rh = (__half*)pRh;
    __half* Gh = (__half*)pGh;
    for (int t = 0; t < Tt; t++) {
        sgemm_fp16<<<hGrid, 128, GEMM_SMEM, s1>>>(Ah, Rh, Gh);
        sgemm_fp16<<<hGrid, 128, GEMM_SMEM, s2>>>(Ah, Rh + 512, Gh + 512);
        lstm_half<<<256, 256, 0, s1>>>(t, 0);
        lstm_half<<<256, 256, 0, s2>>>(t, 1);
    }

    // join
    cudaEventRecord(ev1, s1);
    cudaEventRecord(ev2, s2);
    cudaStreamWaitEvent(0, ev1, 0);
    cudaStreamWaitEvent(0, ev2, 0);

    proj_kernel<<<(Bb * Nn) / 256, 256>>>(Wp, bp, out);
}